// round 9
// baseline (speedup 1.0000x reference)
#include <cuda_runtime.h>
#include <cuda_bf16.h>
#include <cstdint>

// ---------------------------------------------------------------------------
// DeepTransitionRNN: T=512, B=128, D=256, H=256, L=4
//
//  1) memset(out, 0); memset(g_Hbuf, 0)
//  2) xproj_kernel: XP[t][m][hc][b] = x[t,b,:] @ Wm[:,hc]  (5 x-side mats)
//  3) rnn_kernel: persistent, 128 CTAs = 4 groups (32 batch rows) x 32 CTAs
//     (8 H-columns each). 16 h-side weight slices SMEM-resident (128KB).
//     5 GEMM phases/step. h lives ONLY in a ping-pong L2 buffer; GEMM warps
//     stream it via __ldcg with per-warp partial flag waits (each warp waits
//     only on the 8 producer CTAs of its k-quarter). Per-thread h state is
//     register-carried; there is no smem h reload.
// ---------------------------------------------------------------------------

#define T_STEPS 512
#define BATCH   128
#define DDIM    256
#define HDIM    256
#define NLAYERS 4
#define NMAT    16
#define GROUPS  4
#define RPG     32          // batch rows per group
#define CPC     8           // H columns per CTA
#define CPG     32          // CTAs per group
#define XP_MS   (HDIM*BATCH)

typedef unsigned long long ull;

// ---- device scratch (static globals: allocation-free) ----------------------
__device__ __align__(16)  float    g_XP[(size_t)T_STEPS * 5 * HDIM * BATCH];
__device__ __align__(16)  float    g_Hbuf[2][GROUPS][HDIM * RPG];
__device__ __align__(128) unsigned g_flag[GROUPS][CPG];   // monotonic counters

// ---- activations (fp32, error ~1e-7) ---------------------------------------
__device__ __forceinline__ float sigmoidf_(float x) {
    x = fminf(fmaxf(x, -30.f), 30.f);
    return 1.f / (1.f + __expf(-x));
}
__device__ __forceinline__ float tanhf_(float x) {
    x = fminf(fmaxf(x, -15.f), 15.f);
    float e = __expf(2.f * x);
    return (e - 1.f) / (e + 1.f);
}

#define FMA2(acc, a, b) \
    asm("fma.rn.f32x2 %0,%1,%2,%0;" : "+l"(acc) : "l"(a), "l"(b))
#define PACK2(d, s) \
    asm("mov.b64 %0,{%1,%1};" : "=l"(d) : "f"(s))
#define UNPK(s, lo, hi) \
    asm("mov.b64 {%0,%1},%2;" : "=f"(lo), "=f"(hi) : "l"(s))

// ---------------------------------------------------------------------------
// Kernel 1: x-projection GEMM (validated in R7/R8, unchanged).
// ---------------------------------------------------------------------------
__global__ void __launch_bounds__(256) xproj_kernel(
    const float* __restrict__ x,
    const float* __restrict__ Wr, const float* __restrict__ Wz,
    const float* __restrict__ Wl, const float* __restrict__ Cx,
    const float* __restrict__ Wt)
{
    __shared__ float AsmT[16 * 68];
    __shared__ float Bsm [16 * 68];
    __shared__ float Csm [64 * 68];

    const int tid   = threadIdx.x;
    const int bn    = blockIdx.x;
    const int bm    = blockIdx.y;
    const int t     = bm >> 1;
    const int brow0 = (bm & 1) * 64;
    const int n0    = bn * 64;
    const int mat   = n0 >> 8;
    const int hc0   = n0 & 255;
    const float* Wsrc = (mat == 0) ? Wr : (mat == 1) ? Wz :
                        (mat == 2) ? Wl : (mat == 3) ? Cx : Wt;

    const int ty = tid >> 4;
    const int tx = tid & 15;

    ull acc[4][2];
    #pragma unroll
    for (int i = 0; i < 4; ++i) { acc[i][0] = 0ull; acc[i][1] = 0ull; }

    const int a_m = tid >> 2;
    const int a_k = (tid & 3) * 4;
    const int b_k = tid >> 4;
    const int b_c = (tid & 15) * 4;

    const float* ag = x + ((size_t)(t * BATCH + brow0 + a_m)) * DDIM + a_k;
    const float* bg = Wsrc + (size_t)b_k * HDIM + hc0 + b_c;

    for (int k0 = 0; k0 < DDIM; k0 += 16) {
        float4 av = *(const float4*)(ag + k0);
        AsmT[(a_k + 0) * 68 + a_m] = av.x;
        AsmT[(a_k + 1) * 68 + a_m] = av.y;
        AsmT[(a_k + 2) * 68 + a_m] = av.z;
        AsmT[(a_k + 3) * 68 + a_m] = av.w;
        float4 bv = *(const float4*)(bg + (size_t)k0 * HDIM);
        *(float4*)&Bsm[b_k * 68 + b_c] = bv;
        __syncthreads();

        #pragma unroll
        for (int k = 0; k < 16; ++k) {
            float4 a4 = *(const float4*)&AsmT[k * 68 + ty * 4];
            ulonglong2 wv = *(const ulonglong2*)&Bsm[k * 68 + tx * 4];
            ull a2;
            #define XPROJ_STEP(i, comp)                                          \
                PACK2(a2, comp);                                                 \
                FMA2(acc[i][0], a2, wv.x);                                       \
                FMA2(acc[i][1], a2, wv.y);
            XPROJ_STEP(0, a4.x)
            XPROJ_STEP(1, a4.y)
            XPROJ_STEP(2, a4.z)
            XPROJ_STEP(3, a4.w)
            #undef XPROJ_STEP
        }
        __syncthreads();
    }

    #pragma unroll
    for (int i = 0; i < 4; ++i) {
        float c0, c1, c2, c3;
        UNPK(acc[i][0], c0, c1);
        UNPK(acc[i][1], c2, c3);
        Csm[(tx * 4 + 0) * 68 + ty * 4 + i] = c0;
        Csm[(tx * 4 + 1) * 68 + ty * 4 + i] = c1;
        Csm[(tx * 4 + 2) * 68 + ty * 4 + i] = c2;
        Csm[(tx * 4 + 3) * 68 + ty * 4 + i] = c3;
    }
    __syncthreads();

    const int nl = tid >> 2;
    const int mq = tid & 3;
    float* dst = g_XP + ((size_t)((t * 5 + mat) * HDIM + hc0 + nl)) * BATCH
                 + brow0 + mq * 16;
    #pragma unroll
    for (int q = 0; q < 4; ++q) {
        float4 v = *(const float4*)&Csm[nl * 68 + mq * 16 + q * 4];
        *(float4*)(dst + q * 4) = v;
    }
}

// ---------------------------------------------------------------------------
// Recurrence helpers
// ---------------------------------------------------------------------------

// per-warp partial wait: only the 8 producer CTAs of k-quarter kq.
// All lanes load (coalesced 32B), ballot until all >= target, then syncwarp
// so every lane's subsequent loads are ordered after every acquire.
__device__ __forceinline__ void wait_kq(unsigned* flags, int kq,
                                        unsigned target, int lane) {
    unsigned* fp = flags + kq * 8 + (lane & 7);
    unsigned v;
    do {
        asm volatile("ld.acquire.gpu.global.u32 %0,[%1];"
                     : "=r"(v) : "l"(fp) : "memory");
    } while (__ballot_sync(0xffffffffu, v < target));
    __syncwarp();
}

// arrive: bar.sync (CTA-wide happens-before), then ONE release store.
__device__ __forceinline__ void barrier_arrive(unsigned* flags, int cb,
                                               unsigned target, int tid) {
    __syncthreads();
    if (tid == 0)
        asm volatile("st.release.gpu.global.u32 [%0],%1;"
                     :: "l"(flags + cb), "r"(target) : "memory");
}

// dual-matrix GEMM over one k-quarter (64 k): 32 rows x 8 cols x 2 matrices.
// h streamed from the global (L2) buffer with a depth-2 prefetch pipeline.
__device__ __forceinline__ void gemm_dual(
    const float* __restrict__ hp,   // hbuf + kq*2048 + lane
    const float* __restrict__ wa,   // Wsm + matA*2048 + kq*512
    const float* __restrict__ wb,   // Wsm + matB*2048 + kq*512
    float* __restrict__ ga,         // Gp + (kq*4+matA)*256 + lane
    float* __restrict__ gb)
{
    ull A0=0,A1=0,A2=0,A3=0,B0=0,B1=0,B2=0,B3=0;
    float h0[8], h1[8];
    #pragma unroll
    for (int i = 0; i < 8; ++i) h0[i] = __ldcg(hp + i * 32);
    #pragma unroll
    for (int i = 0; i < 8; ++i) h1[i] = __ldcg(hp + 256 + i * 32);

    #pragma unroll 2
    for (int kb = 0; kb < 64; kb += 8) {
        float hn[8];
        if (kb < 48) {
            #pragma unroll
            for (int i = 0; i < 8; ++i)
                hn[i] = __ldcg(hp + (kb + 16 + i) * 32);
        }
        #pragma unroll
        for (int i = 0; i < 8; ++i) {
            ull ad; PACK2(ad, h0[i]);
            const float* wka = wa + (kb + i) * 8;
            const float* wkb = wb + (kb + i) * 8;
            ulonglong2 wa1 = *(const ulonglong2*)(wka);
            ulonglong2 wa2 = *(const ulonglong2*)(wka + 4);
            ulonglong2 wb1 = *(const ulonglong2*)(wkb);
            ulonglong2 wb2 = *(const ulonglong2*)(wkb + 4);
            FMA2(A0, ad, wa1.x); FMA2(A1, ad, wa1.y);
            FMA2(A2, ad, wa2.x); FMA2(A3, ad, wa2.y);
            FMA2(B0, ad, wb1.x); FMA2(B1, ad, wb1.y);
            FMA2(B2, ad, wb2.x); FMA2(B3, ad, wb2.y);
        }
        #pragma unroll
        for (int i = 0; i < 8; ++i) h0[i] = h1[i];
        if (kb < 48) {
            #pragma unroll
            for (int i = 0; i < 8; ++i) h1[i] = hn[i];
        }
    }
    float lo, hi;
    UNPK(A0, lo, hi); ga[0*32] = lo; ga[1*32] = hi;
    UNPK(A1, lo, hi); ga[2*32] = lo; ga[3*32] = hi;
    UNPK(A2, lo, hi); ga[4*32] = lo; ga[5*32] = hi;
    UNPK(A3, lo, hi); ga[6*32] = lo; ga[7*32] = hi;
    UNPK(B0, lo, hi); gb[0*32] = lo; gb[1*32] = hi;
    UNPK(B1, lo, hi); gb[2*32] = lo; gb[3*32] = hi;
    UNPK(B2, lo, hi); gb[4*32] = lo; gb[5*32] = hi;
    UNPK(B3, lo, hi); gb[6*32] = lo; gb[7*32] = hi;
}

// single-matrix variant (transition middle matrix)
__device__ __forceinline__ void gemm_single(
    const float* __restrict__ hp,
    const float* __restrict__ wa,
    float* __restrict__ ga)
{
    ull A0=0,A1=0,A2=0,A3=0;
    float h0[8], h1[8];
    #pragma unroll
    for (int i = 0; i < 8; ++i) h0[i] = __ldcg(hp + i * 32);
    #pragma unroll
    for (int i = 0; i < 8; ++i) h1[i] = __ldcg(hp + 256 + i * 32);

    #pragma unroll 2
    for (int kb = 0; kb < 64; kb += 8) {
        float hn[8];
        if (kb < 48) {
            #pragma unroll
            for (int i = 0; i < 8; ++i)
                hn[i] = __ldcg(hp + (kb + 16 + i) * 32);
        }
        #pragma unroll
        for (int i = 0; i < 8; ++i) {
            ull ad; PACK2(ad, h0[i]);
            const float* wka = wa + (kb + i) * 8;
            ulonglong2 wa1 = *(const ulonglong2*)(wka);
            ulonglong2 wa2 = *(const ulonglong2*)(wka + 4);
            FMA2(A0, ad, wa1.x); FMA2(A1, ad, wa1.y);
            FMA2(A2, ad, wa2.x); FMA2(A3, ad, wa2.y);
        }
        #pragma unroll
        for (int i = 0; i < 8; ++i) h0[i] = h1[i];
        if (kb < 48) {
            #pragma unroll
            for (int i = 0; i < 8; ++i) h1[i] = hn[i];
        }
    }
    float lo, hi;
    UNPK(A0, lo, hi); ga[0*32] = lo; ga[1*32] = hi;
    UNPK(A1, lo, hi); ga[2*32] = lo; ga[3*32] = hi;
    UNPK(A2, lo, hi); ga[4*32] = lo; ga[5*32] = hi;
    UNPK(A3, lo, hi); ga[6*32] = lo; ga[7*32] = hi;
}

// ---------------------------------------------------------------------------
// Kernel 2: the recurrence. 128 CTAs x 256 threads, persistent.
// Dynamic smem: Wsm 16x256x8 (128KB) | Gp 4(kq) x 4(mat) x 256 (16KB)
// ---------------------------------------------------------------------------
#define SMEM_FLOATS (NMAT*HDIM*CPC + 4*4*256)
#define SMEM_BYTES  (SMEM_FLOATS * 4)

__global__ void __launch_bounds__(256, 1) rnn_kernel(
    const float* __restrict__ Wr, const float* __restrict__ Wz,
    const float* __restrict__ Wl, const float* __restrict__ Ch,
    const float* __restrict__ Tr, const float* __restrict__ Tz,
    const float* __restrict__ Tn,
    const int*   __restrict__ lengths,
    float*       __restrict__ out)
{
    extern __shared__ float smem[];
    float* Wsm = smem;                       // 32768 floats
    float* Gp  = smem + NMAT * HDIM * CPC;   //  4096 floats
    __shared__ unsigned sF0;

    const int tid  = threadIdx.x;
    const int cta  = blockIdx.x;
    const int g    = cta >> 5;
    const int cb   = cta & 31;
    const int col0 = cb * CPC;

    // ---- load this CTA's 8-column slice of all 16 h-side matrices ----------
    for (int idx = tid; idx < NMAT * HDIM * CPC; idx += 256) {
        int m = idx >> 11;
        int k = (idx >> 3) & 255;
        int c = idx & 7;
        const float* src;
        if (m == 0)      src = Wr + (size_t)(DDIM + k) * HDIM;
        else if (m == 1) src = Wz + (size_t)(DDIM + k) * HDIM;
        else if (m == 2) src = Wl + (size_t)(DDIM + k) * HDIM;
        else if (m == 3) src = Ch + (size_t)k * HDIM;
        else {
            int mm = m - 4, layer = mm / 3, which = mm % 3;
            const float* base = (which == 0) ? Tr : (which == 1) ? Tz : Tn;
            src = base + (size_t)layer * HDIM * HDIM + (size_t)k * HDIM;
        }
        Wsm[idx] = src[col0 + c];
    }

    const int r     = tid & 31;       // batch row within group
    const int cl    = tid >> 5;       // local column 0..7
    const int b     = g * RPG + r;
    const int colg  = col0 + cl;
    const int mylen = lengths[b];
    const int Lg    = lengths[g * RPG];   // sorted descending -> group max

    const int w    = tid >> 5;
    const int lane = tid & 31;
    const int ei   = cl * 32 + r;

    unsigned* flags = &g_flag[g][0];
    if (tid == 0) sF0 = *((volatile unsigned*)(flags + cb));
    __syncthreads();
    unsigned p = sF0;                 // last-published flag value

    float* rb = &g_Hbuf[0][g][0];     // zeroed by memset before launch
    float* wb = &g_Hbuf[1][g][0];

    float hown  = 0.f;                // this thread's h[colg][r]

    for (int t = 0; t < Lg; ++t) {
        const bool act = (t < mylen);
        const float hstep = hown;     // h at step start (for masking)

        // prefetch this step's x-projections (hidden under phase-A GEMM)
        const float* xp = g_XP + ((size_t)(t * 5) * HDIM + colg) * BATCH + b;
        float xr = __ldcg(xp + 0 * XP_MS);
        float xz = __ldcg(xp + 1 * XP_MS);
        float xl = __ldcg(xp + 2 * XP_MS);
        float xc = __ldcg(xp + 3 * XP_MS);
        float xw = __ldcg(xp + 4 * XP_MS);

        // ================= phase A: 4 GEMMs (mat-pair x k-quarter jobs) =====
        {
            const int mp = w >> 2, kq = w & 3;
            wait_kq(flags, kq, p, lane);
            gemm_dual(rb + kq * 2048 + lane,
                      Wsm + (2 * mp + 0) * 2048 + kq * 512,
                      Wsm + (2 * mp + 1) * 2048 + kq * 512,
                      Gp + (kq * 4 + 2 * mp + 0) * 256 + lane,
                      Gp + (kq * 4 + 2 * mp + 1) * 256 + lane);
        }
        __syncthreads();
        {
            float gr  = Gp[0*256+ei] + Gp[4*256+ei] + Gp[ 8*256+ei] + Gp[12*256+ei];
            float gz  = Gp[1*256+ei] + Gp[5*256+ei] + Gp[ 9*256+ei] + Gp[13*256+ei];
            float gl  = Gp[2*256+ei] + Gp[6*256+ei] + Gp[10*256+ei] + Gp[14*256+ei];
            float gch = Gp[3*256+ei] + Gp[7*256+ei] + Gp[11*256+ei] + Gp[15*256+ei];
            float rv = sigmoidf_(xr + gr);
            float zv = sigmoidf_(xz + gz);
            float lv = sigmoidf_(xl + gl);
            float nv = tanhf_(xc + rv * gch) + lv * xw;
            float hn = (1.f - zv) * hown + zv * nv;
            hown = hn;
            wb[colg * 32 + r] = hn;
        }
        barrier_arrive(flags, cb, p + 1, tid);
        ++p;
        { float* tmp = rb; rb = wb; wb = tmp; }

        // ================= 4 transition layers (Tr,Tz,Tn) ===================
        #pragma unroll 1
        for (int layer = 0; layer < NLAYERS; ++layer) {
            const int mb = 4 + 3 * layer;
            if (w < 4) {
                const int kq = w;
                wait_kq(flags, kq, p, lane);
                gemm_dual(rb + kq * 2048 + lane,
                          Wsm + (mb + 0) * 2048 + kq * 512,  // Tr
                          Wsm + (mb + 2) * 2048 + kq * 512,  // Tn
                          Gp + (kq * 4 + 0) * 256 + lane,
                          Gp + (kq * 4 + 2) * 256 + lane);
            } else {
                const int kq = w - 4;
                wait_kq(flags, kq, p, lane);
                gemm_single(rb + kq * 2048 + lane,
                            Wsm + (mb + 1) * 2048 + kq * 512, // Tz
                            Gp + (kq * 4 + 1) * 256 + lane);
            }
            __syncthreads();
            {
                float grr = Gp[0*256+ei] + Gp[4*256+ei] + Gp[ 8*256+ei] + Gp[12*256+ei];
                float gzz = Gp[1*256+ei] + Gp[5*256+ei] + Gp[ 9*256+ei] + Gp[13*256+ei];
                float gnn = Gp[2*256+ei] + Gp[6*256+ei] + Gp[10*256+ei] + Gp[14*256+ei];
                float rr = sigmoidf_(grr);
                float zz = sigmoidf_(gzz);
                float nn = tanhf_(rr * gnn);
                float hnew = (1.f - zz) * nn + zz * hown;
                if (layer == NLAYERS - 1) {
                    float val = act ? hnew : hstep;
                    hown = val;
                    wb[colg * 32 + r] = val;
                    if (act)
                        out[((size_t)t * BATCH + b) * HDIM + colg] = hnew;
                } else {
                    hown = hnew;
                    wb[colg * 32 + r] = hnew;
                }
            }
            barrier_arrive(flags, cb, p + 1, tid);
            ++p;
            { float* tmp = rb; rb = wb; wb = tmp; }
        }
    }
}

// ---------------------------------------------------------------------------
// kernel_launch: memsets -> x-projection GEMM -> persistent recurrence
// ---------------------------------------------------------------------------
extern "C" void kernel_launch(void* const* d_in, const int* in_sizes, int n_in,
                              void* d_out, int out_size)
{
    const float* x       = (const float*)d_in[0];
    const int*   lengths = (const int*)  d_in[1];
    const float* Wr      = (const float*)d_in[2];
    const float* Wz      = (const float*)d_in[3];
    const float* Wl      = (const float*)d_in[4];
    const float* Wt      = (const float*)d_in[5];
    const float* Cx      = (const float*)d_in[6];
    const float* Ch      = (const float*)d_in[7];
    const float* Tr      = (const float*)d_in[8];
    const float* Tz      = (const float*)d_in[9];
    const float* Tn      = (const float*)d_in[10];
    float* out = (float*)d_out;
    (void)in_sizes; (void)n_in;

    cudaMemsetAsync(out, 0, (size_t)out_size * sizeof(float));

    // h ping-pong buffer must start as zeros every launch (GEMM reads it
    // directly at t=0; graph replays would otherwise see stale h).
    void* hb_ptr = nullptr;
    cudaGetSymbolAddress(&hb_ptr, g_Hbuf);
    cudaMemsetAsync(hb_ptr, 0, sizeof(float) * 2 * GROUPS * HDIM * RPG);

    dim3 ggrid(20, 1024);
    xproj_kernel<<<ggrid, 256>>>(x, Wr, Wz, Wl, Cx, Wt);

    cudaFuncSetAttribute(rnn_kernel,
                         cudaFuncAttributeMaxDynamicSharedMemorySize,
                         SMEM_BYTES);
    rnn_kernel<<<GROUPS * CPG, 256, SMEM_BYTES>>>(
        Wr, Wz, Wl, Ch, Tr, Tz, Tn, lengths, out);
}

// round 10
// speedup vs baseline: 1.1375x; 1.1375x over previous
#include <cuda_runtime.h>
#include <cuda_bf16.h>
#include <cstdint>

// ---------------------------------------------------------------------------
// DeepTransitionRNN: T=512, B=128, D=256, H=256, L=4
//
//  1) memset(out), memset(g_Hbuf)
//  2) xproj_kernel: XP[t][m][hc][b] = x[t,b,:] @ Wm[:,hc]  (5 x-side mats)
//  3) rnn_kernel: persistent, 128 CTAs = 4 groups (32 batch rows) x 32 CTAs
//     (8 H-columns each). 16 h-side weight slices SMEM-resident (128KB).
//     5 GEMM phases/step. Warp w owns k-slice [32w,32w+32): it waits on the
//     4 producer CTAs of that slice, streams h once from L2 (32 up-front
//     LDGs), and computes ALL matrices of the phase for its slice. Partials
//     reduced in smem by the elementwise pass. h state is register-carried.
// ---------------------------------------------------------------------------

#define T_STEPS 512
#define BATCH   128
#define DDIM    256
#define HDIM    256
#define NLAYERS 4
#define NMAT    16
#define GROUPS  4
#define RPG     32          // batch rows per group
#define CPC     8           // H columns per CTA
#define CPG     32          // CTAs per group
#define XP_MS   (HDIM*BATCH)

typedef unsigned long long ull;

// ---- device scratch (static globals: allocation-free) ----------------------
__device__ __align__(16)  float    g_XP[(size_t)T_STEPS * 5 * HDIM * BATCH];
__device__ __align__(16)  float    g_Hbuf[2][GROUPS][HDIM * RPG];
__device__ __align__(128) unsigned g_flag[GROUPS][CPG];   // monotonic counters

// ---- activations (fp32, error ~1e-7) ---------------------------------------
__device__ __forceinline__ float sigmoidf_(float x) {
    x = fminf(fmaxf(x, -30.f), 30.f);
    return 1.f / (1.f + __expf(-x));
}
__device__ __forceinline__ float tanhf_(float x) {
    x = fminf(fmaxf(x, -15.f), 15.f);
    float e = __expf(2.f * x);
    return (e - 1.f) / (e + 1.f);
}

#define FMA2(acc, a, b) \
    asm("fma.rn.f32x2 %0,%1,%2,%0;" : "+l"(acc) : "l"(a), "l"(b))
#define PACK2(d, s) \
    asm("mov.b64 %0,{%1,%1};" : "=l"(d) : "f"(s))
#define UNPK(s, lo, hi) \
    asm("mov.b64 {%0,%1},%2;" : "=f"(lo), "=f"(hi) : "l"(s))

// ---------------------------------------------------------------------------
// Kernel 1: x-projection GEMM (validated in R7/R8, unchanged).
// ---------------------------------------------------------------------------
__global__ void __launch_bounds__(256) xproj_kernel(
    const float* __restrict__ x,
    const float* __restrict__ Wr, const float* __restrict__ Wz,
    const float* __restrict__ Wl, const float* __restrict__ Cx,
    const float* __restrict__ Wt)
{
    __shared__ float AsmT[16 * 68];
    __shared__ float Bsm [16 * 68];
    __shared__ float Csm [64 * 68];

    const int tid   = threadIdx.x;
    const int bn    = blockIdx.x;
    const int bm    = blockIdx.y;
    const int t     = bm >> 1;
    const int brow0 = (bm & 1) * 64;
    const int n0    = bn * 64;
    const int mat   = n0 >> 8;
    const int hc0   = n0 & 255;
    const float* Wsrc = (mat == 0) ? Wr : (mat == 1) ? Wz :
                        (mat == 2) ? Wl : (mat == 3) ? Cx : Wt;

    const int ty = tid >> 4;
    const int tx = tid & 15;

    ull acc[4][2];
    #pragma unroll
    for (int i = 0; i < 4; ++i) { acc[i][0] = 0ull; acc[i][1] = 0ull; }

    const int a_m = tid >> 2;
    const int a_k = (tid & 3) * 4;
    const int b_k = tid >> 4;
    const int b_c = (tid & 15) * 4;

    const float* ag = x + ((size_t)(t * BATCH + brow0 + a_m)) * DDIM + a_k;
    const float* bg = Wsrc + (size_t)b_k * HDIM + hc0 + b_c;

    for (int k0 = 0; k0 < DDIM; k0 += 16) {
        float4 av = *(const float4*)(ag + k0);
        AsmT[(a_k + 0) * 68 + a_m] = av.x;
        AsmT[(a_k + 1) * 68 + a_m] = av.y;
        AsmT[(a_k + 2) * 68 + a_m] = av.z;
        AsmT[(a_k + 3) * 68 + a_m] = av.w;
        float4 bv = *(const float4*)(bg + (size_t)k0 * HDIM);
        *(float4*)&Bsm[b_k * 68 + b_c] = bv;
        __syncthreads();

        #pragma unroll
        for (int k = 0; k < 16; ++k) {
            float4 a4 = *(const float4*)&AsmT[k * 68 + ty * 4];
            ulonglong2 wv = *(const ulonglong2*)&Bsm[k * 68 + tx * 4];
            ull a2;
            #define XPROJ_STEP(i, comp)                                          \
                PACK2(a2, comp);                                                 \
                FMA2(acc[i][0], a2, wv.x);                                       \
                FMA2(acc[i][1], a2, wv.y);
            XPROJ_STEP(0, a4.x)
            XPROJ_STEP(1, a4.y)
            XPROJ_STEP(2, a4.z)
            XPROJ_STEP(3, a4.w)
            #undef XPROJ_STEP
        }
        __syncthreads();
    }

    #pragma unroll
    for (int i = 0; i < 4; ++i) {
        float c0, c1, c2, c3;
        UNPK(acc[i][0], c0, c1);
        UNPK(acc[i][1], c2, c3);
        Csm[(tx * 4 + 0) * 68 + ty * 4 + i] = c0;
        Csm[(tx * 4 + 1) * 68 + ty * 4 + i] = c1;
        Csm[(tx * 4 + 2) * 68 + ty * 4 + i] = c2;
        Csm[(tx * 4 + 3) * 68 + ty * 4 + i] = c3;
    }
    __syncthreads();

    const int nl = tid >> 2;
    const int mq = tid & 3;
    float* dst = g_XP + ((size_t)((t * 5 + mat) * HDIM + hc0 + nl)) * BATCH
                 + brow0 + mq * 16;
    #pragma unroll
    for (int q = 0; q < 4; ++q) {
        float4 v = *(const float4*)&Csm[nl * 68 + mq * 16 + q * 4];
        *(float4*)(dst + q * 4) = v;
    }
}

// ---------------------------------------------------------------------------
// Recurrence helpers
// ---------------------------------------------------------------------------

// warp w waits on the 4 CTAs producing its k-slice [32w, 32w+32).
// 8 lanes per flag word -> one coalesced 16B load per sweep. Wrap-safe.
__device__ __forceinline__ void wait_slice(unsigned* flags, int w,
                                           unsigned target, int lane) {
    unsigned* fp = flags + w * 4 + (lane & 3);
    unsigned v;
    do {
        asm volatile("ld.acquire.gpu.global.u32 %0,[%1];"
                     : "=r"(v) : "l"(fp) : "memory");
    } while (__ballot_sync(0xffffffffu, (int)(v - target) < 0));
    __syncwarp();
}

// NM matrices x 8 cols x 32 rows over this warp's 32-k slice.
// h streamed from L2 once (32 LDGs up-front, MLP=32), weights broadcast LDS.
template <int NM>
__device__ __forceinline__ void gemm_warp(
    const float* __restrict__ rb,     // group h buffer (read)
    const float* __restrict__ wbase,  // Wsm + first-matrix offset
    float* __restrict__ Gp,           // partials: [w][mat][col*32+row]
    int w, int lane)
{
    ull acc[NM * 4];
    #pragma unroll
    for (int i = 0; i < NM * 4; ++i) acc[i] = 0ull;

    const float* hp = rb + (w << 10) + lane;   // k-slice base, lane = row
    float h0[16], h1[16];
    #pragma unroll
    for (int i = 0; i < 16; ++i) h0[i] = __ldcg(hp + i * 32);
    #pragma unroll
    for (int i = 0; i < 16; ++i) h1[i] = __ldcg(hp + (16 + i) * 32);

    const float* wk = wbase + (w * 32) * 8;    // weights for this k-slice

    #pragma unroll
    for (int i = 0; i < 16; ++i) {
        ull hd; PACK2(hd, h0[i]);
        #pragma unroll
        for (int m = 0; m < NM; ++m) {
            const float* q = wk + m * 2048 + i * 8;
            ulonglong2 wa = *(const ulonglong2*)q;
            ulonglong2 wb = *(const ulonglong2*)(q + 4);
            FMA2(acc[m*4+0], hd, wa.x); FMA2(acc[m*4+1], hd, wa.y);
            FMA2(acc[m*4+2], hd, wb.x); FMA2(acc[m*4+3], hd, wb.y);
        }
    }
    #pragma unroll
    for (int i = 0; i < 16; ++i) {
        ull hd; PACK2(hd, h1[i]);
        #pragma unroll
        for (int m = 0; m < NM; ++m) {
            const float* q = wk + m * 2048 + (16 + i) * 8;
            ulonglong2 wa = *(const ulonglong2*)q;
            ulonglong2 wb = *(const ulonglong2*)(q + 4);
            FMA2(acc[m*4+0], hd, wa.x); FMA2(acc[m*4+1], hd, wa.y);
            FMA2(acc[m*4+2], hd, wb.x); FMA2(acc[m*4+3], hd, wb.y);
        }
    }

    float* gp = Gp + (w * 4) * 256 + lane;
    #pragma unroll
    for (int m = 0; m < NM; ++m) {
        #pragma unroll
        for (int cp = 0; cp < 4; ++cp) {
            float lo, hi;
            UNPK(acc[m*4+cp], lo, hi);
            gp[m*256 + (2*cp)   * 32] = lo;
            gp[m*256 + (2*cp+1) * 32] = hi;
        }
    }
}

// ---------------------------------------------------------------------------
// Kernel 2: the recurrence. 128 CTAs x 256 threads, persistent.
// Dynamic smem: Wsm 16x256x8 (128KB) | Gp 8(w) x 4(mat) x 256 (32KB)
// ---------------------------------------------------------------------------
#define SMEM_FLOATS (NMAT*HDIM*CPC + 8*4*256)
#define SMEM_BYTES  (SMEM_FLOATS * 4)

__global__ void __launch_bounds__(256, 1) rnn_kernel(
    const float* __restrict__ Wr, const float* __restrict__ Wz,
    const float* __restrict__ Wl, const float* __restrict__ Ch,
    const float* __restrict__ Tr, const float* __restrict__ Tz,
    const float* __restrict__ Tn,
    const int*   __restrict__ lengths,
    float*       __restrict__ out)
{
    extern __shared__ float smem[];
    float* Wsm = smem;                       // 32768 floats
    float* Gp  = smem + NMAT * HDIM * CPC;   //  8192 floats
    __shared__ unsigned sF0;

    const int tid  = threadIdx.x;
    const int cta  = blockIdx.x;
    const int g    = cta >> 5;
    const int cb   = cta & 31;
    const int col0 = cb * CPC;

    // ---- load this CTA's 8-column slice of all 16 h-side matrices ----------
    for (int idx = tid; idx < NMAT * HDIM * CPC; idx += 256) {
        int m = idx >> 11;
        int k = (idx >> 3) & 255;
        int c = idx & 7;
        const float* src;
        if (m == 0)      src = Wr + (size_t)(DDIM + k) * HDIM;
        else if (m == 1) src = Wz + (size_t)(DDIM + k) * HDIM;
        else if (m == 2) src = Wl + (size_t)(DDIM + k) * HDIM;
        else if (m == 3) src = Ch + (size_t)k * HDIM;
        else {
            int mm = m - 4, layer = mm / 3, which = mm % 3;
            const float* base = (which == 0) ? Tr : (which == 1) ? Tz : Tn;
            src = base + (size_t)layer * HDIM * HDIM + (size_t)k * HDIM;
        }
        Wsm[idx] = src[col0 + c];
    }

    const int r     = tid & 31;       // batch row within group (also GEMM lane)
    const int cl    = tid >> 5;       // local column (also GEMM warp id)
    const int b     = g * RPG + r;
    const int colg  = col0 + cl;
    const int mylen = lengths[b];
    const int Lg    = lengths[g * RPG];   // sorted descending -> group max

    const int w    = cl;              // warp id
    const int lane = r;

    unsigned* flags = &g_flag[g][0];
    if (tid == 0) sF0 = *((volatile unsigned*)(flags + cb));
    __syncthreads();
    unsigned p = sF0;                 // data level consumed by next GEMM

    float* rb = &g_Hbuf[0][g][0];     // zeroed by memset before launch
    float* wb = &g_Hbuf[1][g][0];

    float hown = 0.f;                 // this thread's h[colg][r]

    for (int t = 0; t < Lg; ++t) {
        const bool act = (t < mylen);
        const float hstep = hown;

        // prefetch this step's x-projections (hidden under phase-A GEMM)
        const float* xp = g_XP + ((size_t)(t * 5) * HDIM + colg) * BATCH + b;
        float xr = __ldcg(xp + 0 * XP_MS);
        float xz = __ldcg(xp + 1 * XP_MS);
        float xl = __ldcg(xp + 2 * XP_MS);
        float xc = __ldcg(xp + 3 * XP_MS);
        float xw = __ldcg(xp + 4 * XP_MS);

        // ================= phase A: 4 GEMMs, warp = k-slice ==================
        wait_slice(flags, w, p, lane);
        gemm_warp<4>(rb, Wsm, Gp, w, lane);
        __syncthreads();
        {
            float gr = 0.f, gz = 0.f, gl = 0.f, gch = 0.f;
            #pragma unroll
            for (int ww = 0; ww < 8; ++ww) {
                const float* q = Gp + ww * 1024 + tid;
                gr += q[0]; gz += q[256]; gl += q[512]; gch += q[768];
            }
            float rv = sigmoidf_(xr + gr);
            float zv = sigmoidf_(xz + gz);
            float lv = sigmoidf_(xl + gl);
            float nv = tanhf_(xc + rv * gch) + lv * xw;
            hown = (1.f - zv) * hown + zv * nv;
            wb[cb * 256 + tid] = hown;
        }
        __syncthreads();
        if (tid == 0)
            asm volatile("st.release.gpu.global.u32 [%0],%1;"
                         :: "l"(flags + cb), "r"(p + 1) : "memory");
        ++p;
        { float* tmp = rb; rb = wb; wb = tmp; }

        // ================= 4 transition layers (Tr,Tz,Tn) ===================
        #pragma unroll 1
        for (int layer = 0; layer < NLAYERS; ++layer) {
            wait_slice(flags, w, p, lane);
            gemm_warp<3>(rb, Wsm + (4 + 3 * layer) * 2048, Gp, w, lane);
            __syncthreads();
            {
                float grr = 0.f, gzz = 0.f, gnn = 0.f;
                #pragma unroll
                for (int ww = 0; ww < 8; ++ww) {
                    const float* q = Gp + ww * 1024 + tid;
                    grr += q[0]; gzz += q[256]; gnn += q[512];
                }
                float rr = sigmoidf_(grr);
                float zz = sigmoidf_(gzz);
                float nn = tanhf_(rr * gnn);
                float hnew = (1.f - zz) * nn + zz * hown;
                if (layer == NLAYERS - 1) {
                    hown = act ? hnew : hstep;
                    wb[cb * 256 + tid] = hown;
                    if (act)
                        out[((size_t)t * BATCH + b) * HDIM + colg] = hnew;
                } else {
                    hown = hnew;
                    wb[cb * 256 + tid] = hnew;
                }
            }
            __syncthreads();
            if (tid == 0)
                asm volatile("st.release.gpu.global.u32 [%0],%1;"
                             :: "l"(flags + cb), "r"(p + 1) : "memory");
            ++p;
            { float* tmp = rb; rb = wb; wb = tmp; }
        }
    }
}

// ---------------------------------------------------------------------------
// kernel_launch: memsets -> x-projection GEMM -> persistent recurrence
// ---------------------------------------------------------------------------
extern "C" void kernel_launch(void* const* d_in, const int* in_sizes, int n_in,
                              void* d_out, int out_size)
{
    const float* x       = (const float*)d_in[0];
    const int*   lengths = (const int*)  d_in[1];
    const float* Wr      = (const float*)d_in[2];
    const float* Wz      = (const float*)d_in[3];
    const float* Wl      = (const float*)d_in[4];
    const float* Wt      = (const float*)d_in[5];
    const float* Cx      = (const float*)d_in[6];
    const float* Ch      = (const float*)d_in[7];
    const float* Tr      = (const float*)d_in[8];
    const float* Tz      = (const float*)d_in[9];
    const float* Tn      = (const float*)d_in[10];
    float* out = (float*)d_out;
    (void)in_sizes; (void)n_in;

    cudaMemsetAsync(out, 0, (size_t)out_size * sizeof(float));

    // h ping-pong buffer must start as zeros every launch (GEMM reads it at
    // t=0; graph replays would otherwise see stale h).
    void* hb_ptr = nullptr;
    cudaGetSymbolAddress(&hb_ptr, g_Hbuf);
    cudaMemsetAsync(hb_ptr, 0, sizeof(float) * 2 * GROUPS * HDIM * RPG);

    dim3 ggrid(20, 1024);
    xproj_kernel<<<ggrid, 256>>>(x, Wr, Wz, Wl, Cx, Wt);

    cudaFuncSetAttribute(rnn_kernel,
                         cudaFuncAttributeMaxDynamicSharedMemorySize,
                         SMEM_BYTES);
    rnn_kernel<<<GROUPS * CPG, 256, SMEM_BYTES>>>(
        Wr, Wz, Wl, Ch, Tr, Tz, Tn, lengths, out);
}

// round 11
// speedup vs baseline: 1.4087x; 1.2385x over previous
#include <cuda_runtime.h>
#include <cuda_bf16.h>
#include <cstdint>

// ---------------------------------------------------------------------------
// DeepTransitionRNN: T=512, B=128, D=256, H=256, L=4
//
//  1) memset(out), memset(g_Hbuf)
//  2) xproj_kernel: XP[t][m][hc][b] = x[t,b,:] @ Wm[:,hc]  (5 x-side mats)
//  3) rnn_kernel: persistent, 128 CTAs = 4 groups (32 batch rows) x 32 CTAs
//     (8 H-columns each). 16 h-side weight slices SMEM-resident (128KB).
//     5 GEMM phases/step. Sync = R8 scheme (ONLY warp 0 polls the group's 32
//     flags, one coalesced 128B acquire-load per sweep; other warps wait in
//     bar.sync) -- minimizes LTS polling contention. GEMM = R10 scheme (warp
//     w owns k-slice [32w,32w+32), streams h once from L2 with 32 up-front
//     LDGs, computes ALL matrices of the phase; partials reduced in smem).
//     h state is register-carried; no smem h staging.
// ---------------------------------------------------------------------------

#define T_STEPS 512
#define BATCH   128
#define DDIM    256
#define HDIM    256
#define NLAYERS 4
#define NMAT    16
#define GROUPS  4
#define RPG     32          // batch rows per group
#define CPC     8           // H columns per CTA
#define CPG     32          // CTAs per group
#define XP_MS   (HDIM*BATCH)

typedef unsigned long long ull;

// ---- device scratch (static globals: allocation-free) ----------------------
__device__ __align__(16)  float    g_XP[(size_t)T_STEPS * 5 * HDIM * BATCH];
__device__ __align__(16)  float    g_Hbuf[2][GROUPS][HDIM * RPG];
__device__ __align__(128) unsigned g_flag[GROUPS][CPG];   // monotonic counters

// ---- activations (fp32, error ~1e-7) ---------------------------------------
__device__ __forceinline__ float sigmoidf_(float x) {
    x = fminf(fmaxf(x, -30.f), 30.f);
    return 1.f / (1.f + __expf(-x));
}
__device__ __forceinline__ float tanhf_(float x) {
    x = fminf(fmaxf(x, -15.f), 15.f);
    float e = __expf(2.f * x);
    return (e - 1.f) / (e + 1.f);
}

#define FMA2(acc, a, b) \
    asm("fma.rn.f32x2 %0,%1,%2,%0;" : "+l"(acc) : "l"(a), "l"(b))
#define PACK2(d, s) \
    asm("mov.b64 %0,{%1,%1};" : "=l"(d) : "f"(s))
#define UNPK(s, lo, hi) \
    asm("mov.b64 {%0,%1},%2;" : "=f"(lo), "=f"(hi) : "l"(s))

// ---------------------------------------------------------------------------
// Kernel 1: x-projection GEMM (validated R7-R10, unchanged).
// ---------------------------------------------------------------------------
__global__ void __launch_bounds__(256) xproj_kernel(
    const float* __restrict__ x,
    const float* __restrict__ Wr, const float* __restrict__ Wz,
    const float* __restrict__ Wl, const float* __restrict__ Cx,
    const float* __restrict__ Wt)
{
    __shared__ float AsmT[16 * 68];
    __shared__ float Bsm [16 * 68];
    __shared__ float Csm [64 * 68];

    const int tid   = threadIdx.x;
    const int bn    = blockIdx.x;
    const int bm    = blockIdx.y;
    const int t     = bm >> 1;
    const int brow0 = (bm & 1) * 64;
    const int n0    = bn * 64;
    const int mat   = n0 >> 8;
    const int hc0   = n0 & 255;
    const float* Wsrc = (mat == 0) ? Wr : (mat == 1) ? Wz :
                        (mat == 2) ? Wl : (mat == 3) ? Cx : Wt;

    const int ty = tid >> 4;
    const int tx = tid & 15;

    ull acc[4][2];
    #pragma unroll
    for (int i = 0; i < 4; ++i) { acc[i][0] = 0ull; acc[i][1] = 0ull; }

    const int a_m = tid >> 2;
    const int a_k = (tid & 3) * 4;
    const int b_k = tid >> 4;
    const int b_c = (tid & 15) * 4;

    const float* ag = x + ((size_t)(t * BATCH + brow0 + a_m)) * DDIM + a_k;
    const float* bg = Wsrc + (size_t)b_k * HDIM + hc0 + b_c;

    for (int k0 = 0; k0 < DDIM; k0 += 16) {
        float4 av = *(const float4*)(ag + k0);
        AsmT[(a_k + 0) * 68 + a_m] = av.x;
        AsmT[(a_k + 1) * 68 + a_m] = av.y;
        AsmT[(a_k + 2) * 68 + a_m] = av.z;
        AsmT[(a_k + 3) * 68 + a_m] = av.w;
        float4 bv = *(const float4*)(bg + (size_t)k0 * HDIM);
        *(float4*)&Bsm[b_k * 68 + b_c] = bv;
        __syncthreads();

        #pragma unroll
        for (int k = 0; k < 16; ++k) {
            float4 a4 = *(const float4*)&AsmT[k * 68 + ty * 4];
            ulonglong2 wv = *(const ulonglong2*)&Bsm[k * 68 + tx * 4];
            ull a2;
            #define XPROJ_STEP(i, comp)                                          \
                PACK2(a2, comp);                                                 \
                FMA2(acc[i][0], a2, wv.x);                                       \
                FMA2(acc[i][1], a2, wv.y);
            XPROJ_STEP(0, a4.x)
            XPROJ_STEP(1, a4.y)
            XPROJ_STEP(2, a4.z)
            XPROJ_STEP(3, a4.w)
            #undef XPROJ_STEP
        }
        __syncthreads();
    }

    #pragma unroll
    for (int i = 0; i < 4; ++i) {
        float c0, c1, c2, c3;
        UNPK(acc[i][0], c0, c1);
        UNPK(acc[i][1], c2, c3);
        Csm[(tx * 4 + 0) * 68 + ty * 4 + i] = c0;
        Csm[(tx * 4 + 1) * 68 + ty * 4 + i] = c1;
        Csm[(tx * 4 + 2) * 68 + ty * 4 + i] = c2;
        Csm[(tx * 4 + 3) * 68 + ty * 4 + i] = c3;
    }
    __syncthreads();

    const int nl = tid >> 2;
    const int mq = tid & 3;
    float* dst = g_XP + ((size_t)((t * 5 + mat) * HDIM + hc0 + nl)) * BATCH
                 + brow0 + mq * 16;
    #pragma unroll
    for (int q = 0; q < 4; ++q) {
        float4 v = *(const float4*)&Csm[nl * 68 + mq * 16 + q * 4];
        *(float4*)(dst + q * 4) = v;
    }
}

// ---------------------------------------------------------------------------
// Recurrence helpers
// ---------------------------------------------------------------------------

// Full-group wait, R8-style: ONLY warp 0 polls (32 lanes cover the group's 32
// flags -> one coalesced 128B acquire-load per sweep); all other warps park in
// bar.sync. Minimizes LTS polling traffic. Wrap-safe compare.
__device__ __forceinline__ void wait_group(unsigned* flags, unsigned target,
                                           int tid) {
    if (tid < 32) {
        unsigned v;
        do {
            asm volatile("ld.acquire.gpu.global.u32 %0,[%1];"
                         : "=r"(v) : "l"(flags + tid) : "memory");
        } while (__ballot_sync(0xffffffffu, (int)(v - target) < 0));
    }
    __syncthreads();   // joins + propagates the acquired visibility CTA-wide
}

// NM matrices x 8 cols x 32 rows over this warp's 32-k slice.
// h streamed from L2 once (32 LDGs up-front, MLP=32), weights broadcast LDS.
template <int NM>
__device__ __forceinline__ void gemm_warp(
    const float* __restrict__ rb,     // group h buffer (read)
    const float* __restrict__ wbase,  // Wsm + first-matrix offset
    float* __restrict__ Gp,           // partials: [w][mat][col*32+row]
    int w, int lane)
{
    ull acc[NM * 4];
    #pragma unroll
    for (int i = 0; i < NM * 4; ++i) acc[i] = 0ull;

    const float* hp = rb + (w << 10) + lane;   // k-slice base, lane = row
    float h0[16], h1[16];
    #pragma unroll
    for (int i = 0; i < 16; ++i) h0[i] = __ldcg(hp + i * 32);
    #pragma unroll
    for (int i = 0; i < 16; ++i) h1[i] = __ldcg(hp + (16 + i) * 32);

    const float* wk = wbase + (w * 32) * 8;    // weights for this k-slice

    #pragma unroll
    for (int i = 0; i < 16; ++i) {
        ull hd; PACK2(hd, h0[i]);
        #pragma unroll
        for (int m = 0; m < NM; ++m) {
            const float* q = wk + m * 2048 + i * 8;
            ulonglong2 wa = *(const ulonglong2*)q;
            ulonglong2 wb = *(const ulonglong2*)(q + 4);
            FMA2(acc[m*4+0], hd, wa.x); FMA2(acc[m*4+1], hd, wa.y);
            FMA2(acc[m*4+2], hd, wb.x); FMA2(acc[m*4+3], hd, wb.y);
        }
    }
    #pragma unroll
    for (int i = 0; i < 16; ++i) {
        ull hd; PACK2(hd, h1[i]);
        #pragma unroll
        for (int m = 0; m < NM; ++m) {
            const float* q = wk + m * 2048 + (16 + i) * 8;
            ulonglong2 wa = *(const ulonglong2*)q;
            ulonglong2 wb = *(const ulonglong2*)(q + 4);
            FMA2(acc[m*4+0], hd, wa.x); FMA2(acc[m*4+1], hd, wa.y);
            FMA2(acc[m*4+2], hd, wb.x); FMA2(acc[m*4+3], hd, wb.y);
        }
    }

    float* gp = Gp + (w * 4) * 256 + lane;
    #pragma unroll
    for (int m = 0; m < NM; ++m) {
        #pragma unroll
        for (int cp = 0; cp < 4; ++cp) {
            float lo, hi;
            UNPK(acc[m*4+cp], lo, hi);
            gp[m*256 + (2*cp)   * 32] = lo;
            gp[m*256 + (2*cp+1) * 32] = hi;
        }
    }
}

// ---------------------------------------------------------------------------
// Kernel 2: the recurrence. 128 CTAs x 256 threads, persistent.
// Dynamic smem: Wsm 16x256x8 (128KB) | Gp 8(w) x 4(mat) x 256 (32KB)
// ---------------------------------------------------------------------------
#define SMEM_FLOATS (NMAT*HDIM*CPC + 8*4*256)
#define SMEM_BYTES  (SMEM_FLOATS * 4)

__global__ void __launch_bounds__(256, 1) rnn_kernel(
    const float* __restrict__ Wr, const float* __restrict__ Wz,
    const float* __restrict__ Wl, const float* __restrict__ Ch,
    const float* __restrict__ Tr, const float* __restrict__ Tz,
    const float* __restrict__ Tn,
    const int*   __restrict__ lengths,
    float*       __restrict__ out)
{
    extern __shared__ float smem[];
    float* Wsm = smem;                       // 32768 floats
    float* Gp  = smem + NMAT * HDIM * CPC;   //  8192 floats
    __shared__ unsigned sF0;

    const int tid  = threadIdx.x;
    const int cta  = blockIdx.x;
    const int g    = cta >> 5;
    const int cb   = cta & 31;
    const int col0 = cb * CPC;

    // ---- load this CTA's 8-column slice of all 16 h-side matrices ----------
    for (int idx = tid; idx < NMAT * HDIM * CPC; idx += 256) {
        int m = idx >> 11;
        int k = (idx >> 3) & 255;
        int c = idx & 7;
        const float* src;
        if (m == 0)      src = Wr + (size_t)(DDIM + k) * HDIM;
        else if (m == 1) src = Wz + (size_t)(DDIM + k) * HDIM;
        else if (m == 2) src = Wl + (size_t)(DDIM + k) * HDIM;
        else if (m == 3) src = Ch + (size_t)k * HDIM;
        else {
            int mm = m - 4, layer = mm / 3, which = mm % 3;
            const float* base = (which == 0) ? Tr : (which == 1) ? Tz : Tn;
            src = base + (size_t)layer * HDIM * HDIM + (size_t)k * HDIM;
        }
        Wsm[idx] = src[col0 + c];
    }

    const int r     = tid & 31;       // batch row within group (also GEMM lane)
    const int cl    = tid >> 5;       // local column (also GEMM warp id)
    const int b     = g * RPG + r;
    const int colg  = col0 + cl;
    const int mylen = lengths[b];
    const int Lg    = lengths[g * RPG];   // sorted descending -> group max

    const int w    = cl;              // warp id
    const int lane = r;

    unsigned* flags = &g_flag[g][0];
    if (tid == 0) sF0 = *((volatile unsigned*)(flags + cb));
    __syncthreads();
    unsigned p = sF0;                 // data level consumed by next GEMM

    float* rb = &g_Hbuf[0][g][0];     // zeroed by memset before launch
    float* wb = &g_Hbuf[1][g][0];

    float hown = 0.f;                 // this thread's h[colg][r]

    for (int t = 0; t < Lg; ++t) {
        const bool act = (t < mylen);
        const float hstep = hown;

        // prefetch this step's x-projections (hidden under phase-A GEMM)
        const float* xp = g_XP + ((size_t)(t * 5) * HDIM + colg) * BATCH + b;
        float xr = __ldcg(xp + 0 * XP_MS);
        float xz = __ldcg(xp + 1 * XP_MS);
        float xl = __ldcg(xp + 2 * XP_MS);
        float xc = __ldcg(xp + 3 * XP_MS);
        float xw = __ldcg(xp + 4 * XP_MS);

        // ================= phase A: 4 GEMMs, warp = k-slice ==================
        wait_group(flags, p, tid);
        gemm_warp<4>(rb, Wsm, Gp, w, lane);
        __syncthreads();
        {
            float gr = 0.f, gz = 0.f, gl = 0.f, gch = 0.f;
            #pragma unroll
            for (int ww = 0; ww < 8; ++ww) {
                const float* q = Gp + ww * 1024 + tid;
                gr += q[0]; gz += q[256]; gl += q[512]; gch += q[768];
            }
            float rv = sigmoidf_(xr + gr);
            float zv = sigmoidf_(xz + gz);
            float lv = sigmoidf_(xl + gl);
            float nv = tanhf_(xc + rv * gch) + lv * xw;
            hown = (1.f - zv) * hown + zv * nv;
            wb[cb * 256 + tid] = hown;
        }
        __syncthreads();
        if (tid == 0)
            asm volatile("st.release.gpu.global.u32 [%0],%1;"
                         :: "l"(flags + cb), "r"(p + 1) : "memory");
        ++p;
        { float* tmp = rb; rb = wb; wb = tmp; }

        // ================= 4 transition layers (Tr,Tz,Tn) ===================
        #pragma unroll 1
        for (int layer = 0; layer < NLAYERS; ++layer) {
            wait_group(flags, p, tid);
            gemm_warp<3>(rb, Wsm + (4 + 3 * layer) * 2048, Gp, w, lane);
            __syncthreads();
            float outval = 0.f;
            bool  dostore = false;
            {
                float grr = 0.f, gzz = 0.f, gnn = 0.f;
                #pragma unroll
                for (int ww = 0; ww < 8; ++ww) {
                    const float* q = Gp + ww * 1024 + tid;
                    grr += q[0]; gzz += q[256]; gnn += q[512];
                }
                float rr = sigmoidf_(grr);
                float zz = sigmoidf_(gzz);
                float nn = tanhf_(rr * gnn);
                float hnew = (1.f - zz) * nn + zz * hown;
                if (layer == NLAYERS - 1) {
                    hown = act ? hnew : hstep;
                    wb[cb * 256 + tid] = hown;
                    outval  = hnew;
                    dostore = act;
                } else {
                    hown = hnew;
                    wb[cb * 256 + tid] = hnew;
                }
            }
            __syncthreads();
            if (tid == 0)
                asm volatile("st.release.gpu.global.u32 [%0],%1;"
                             :: "l"(flags + cb), "r"(p + 1) : "memory");
            ++p;
            { float* tmp = rb; rb = wb; wb = tmp; }
            // output store AFTER the release: off the critical path
            if (dostore)
                out[((size_t)t * BATCH + b) * HDIM + colg] = outval;
        }
    }
}

// ---------------------------------------------------------------------------
// kernel_launch: memsets -> x-projection GEMM -> persistent recurrence
// ---------------------------------------------------------------------------
extern "C" void kernel_launch(void* const* d_in, const int* in_sizes, int n_in,
                              void* d_out, int out_size)
{
    const float* x       = (const float*)d_in[0];
    const int*   lengths = (const int*)  d_in[1];
    const float* Wr      = (const float*)d_in[2];
    const float* Wz      = (const float*)d_in[3];
    const float* Wl      = (const float*)d_in[4];
    const float* Wt      = (const float*)d_in[5];
    const float* Cx      = (const float*)d_in[6];
    const float* Ch      = (const float*)d_in[7];
    const float* Tr      = (const float*)d_in[8];
    const float* Tz      = (const float*)d_in[9];
    const float* Tn      = (const float*)d_in[10];
    float* out = (float*)d_out;
    (void)in_sizes; (void)n_in;

    cudaMemsetAsync(out, 0, (size_t)out_size * sizeof(float));

    // h ping-pong buffer must start as zeros every launch (GEMM reads it at
    // t=0; graph replays would otherwise see stale h).
    void* hb_ptr = nullptr;
    cudaGetSymbolAddress(&hb_ptr, g_Hbuf);
    cudaMemsetAsync(hb_ptr, 0, sizeof(float) * 2 * GROUPS * HDIM * RPG);

    dim3 ggrid(20, 1024);
    xproj_kernel<<<ggrid, 256>>>(x, Wr, Wz, Wl, Cx, Wt);

    cudaFuncSetAttribute(rnn_kernel,
                         cudaFuncAttributeMaxDynamicSharedMemorySize,
                         SMEM_BYTES);
    rnn_kernel<<<GROUPS * CPG, 256, SMEM_BYTES>>>(
        Wr, Wz, Wl, Ch, Tr, Tz, Tn, lengths, out);
}

// round 12
// speedup vs baseline: 2.0528x; 1.4572x over previous
#include <cuda_runtime.h>
#include <cuda_bf16.h>
#include <cstdint>

// ---------------------------------------------------------------------------
// DeepTransitionRNN: T=512, B=128, D=256, H=256, L=4
//
//  1) memset(out), memset(g_Hbuf: tags -> 0)
//  2) xproj_kernel: XP[t][m][hc][b] = x[t,b,:] @ Wm[:,hc]  (5 x-side mats)
//  3) rnn_kernel: persistent, 128 CTAs = 4 groups (32 batch rows) x 32 CTAs
//     (8 H-columns each). 16 h-side weight slices SMEM-resident (128KB).
//     5 GEMM phases/step. SELF-SYNCHRONIZING h exchange: each h element is an
//     atomic 8B {f32 val, u32 tag} in a 2-deep ping-pong ring; consumers poll
//     the data words themselves (relaxed 8B atomics, per-warp, per-k-chunk).
//     No flags, no fences, no full-group barrier.
// ---------------------------------------------------------------------------

#define T_STEPS 512
#define BATCH   128
#define DDIM    256
#define HDIM    256
#define NLAYERS 4
#define NMAT    16
#define GROUPS  4
#define RPG     32          // batch rows per group
#define CPC     8           // H columns per CTA
#define CPG     32          // CTAs per group
#define XP_MS   (HDIM*BATCH)

typedef unsigned long long ull;

// ---- device scratch (static globals: allocation-free) ----------------------
__device__ __align__(16) float g_XP[(size_t)T_STEPS * 5 * HDIM * BATCH];
__device__ __align__(16) ull   g_Hbuf[2][GROUPS][HDIM * RPG];  // {val, tag}

// ---- activations (fp32, error ~1e-7) ---------------------------------------
__device__ __forceinline__ float sigmoidf_(float x) {
    x = fminf(fmaxf(x, -30.f), 30.f);
    return 1.f / (1.f + __expf(-x));
}
__device__ __forceinline__ float tanhf_(float x) {
    x = fminf(fmaxf(x, -15.f), 15.f);
    float e = __expf(2.f * x);
    return (e - 1.f) / (e + 1.f);
}

#define FMA2(acc, a, b) \
    asm("fma.rn.f32x2 %0,%1,%2,%0;" : "+l"(acc) : "l"(a), "l"(b))
#define PACK2(d, s) \
    asm("mov.b64 %0,{%1,%1};" : "=l"(d) : "f"(s))
#define UNPK(s, lo, hi) \
    asm("mov.b64 {%0,%1},%2;" : "=f"(lo), "=f"(hi) : "l"(s))

__device__ __forceinline__ ull ld_rlx64(const ull* p) {
    ull v;
    asm volatile("ld.relaxed.gpu.global.b64 %0,[%1];"
                 : "=l"(v) : "l"(p) : "memory");
    return v;
}
__device__ __forceinline__ void st_rlx64(ull* p, ull v) {
    asm volatile("st.relaxed.gpu.global.b64 [%0],%1;"
                 :: "l"(p), "l"(v) : "memory");
}

// ---------------------------------------------------------------------------
// Kernel 1: x-projection GEMM (validated R7-R11, unchanged).
// ---------------------------------------------------------------------------
__global__ void __launch_bounds__(256) xproj_kernel(
    const float* __restrict__ x,
    const float* __restrict__ Wr, const float* __restrict__ Wz,
    const float* __restrict__ Wl, const float* __restrict__ Cx,
    const float* __restrict__ Wt)
{
    __shared__ float AsmT[16 * 68];
    __shared__ float Bsm [16 * 68];
    __shared__ float Csm [64 * 68];

    const int tid   = threadIdx.x;
    const int bn    = blockIdx.x;
    const int bm    = blockIdx.y;
    const int t     = bm >> 1;
    const int brow0 = (bm & 1) * 64;
    const int n0    = bn * 64;
    const int mat   = n0 >> 8;
    const int hc0   = n0 & 255;
    const float* Wsrc = (mat == 0) ? Wr : (mat == 1) ? Wz :
                        (mat == 2) ? Wl : (mat == 3) ? Cx : Wt;

    const int ty = tid >> 4;
    const int tx = tid & 15;

    ull acc[4][2];
    #pragma unroll
    for (int i = 0; i < 4; ++i) { acc[i][0] = 0ull; acc[i][1] = 0ull; }

    const int a_m = tid >> 2;
    const int a_k = (tid & 3) * 4;
    const int b_k = tid >> 4;
    const int b_c = (tid & 15) * 4;

    const float* ag = x + ((size_t)(t * BATCH + brow0 + a_m)) * DDIM + a_k;
    const float* bg = Wsrc + (size_t)b_k * HDIM + hc0 + b_c;

    for (int k0 = 0; k0 < DDIM; k0 += 16) {
        float4 av = *(const float4*)(ag + k0);
        AsmT[(a_k + 0) * 68 + a_m] = av.x;
        AsmT[(a_k + 1) * 68 + a_m] = av.y;
        AsmT[(a_k + 2) * 68 + a_m] = av.z;
        AsmT[(a_k + 3) * 68 + a_m] = av.w;
        float4 bv = *(const float4*)(bg + (size_t)k0 * HDIM);
        *(float4*)&Bsm[b_k * 68 + b_c] = bv;
        __syncthreads();

        #pragma unroll
        for (int k = 0; k < 16; ++k) {
            float4 a4 = *(const float4*)&AsmT[k * 68 + ty * 4];
            ulonglong2 wv = *(const ulonglong2*)&Bsm[k * 68 + tx * 4];
            ull a2;
            #define XPROJ_STEP(i, comp)                                          \
                PACK2(a2, comp);                                                 \
                FMA2(acc[i][0], a2, wv.x);                                       \
                FMA2(acc[i][1], a2, wv.y);
            XPROJ_STEP(0, a4.x)
            XPROJ_STEP(1, a4.y)
            XPROJ_STEP(2, a4.z)
            XPROJ_STEP(3, a4.w)
            #undef XPROJ_STEP
        }
        __syncthreads();
    }

    #pragma unroll
    for (int i = 0; i < 4; ++i) {
        float c0, c1, c2, c3;
        UNPK(acc[i][0], c0, c1);
        UNPK(acc[i][1], c2, c3);
        Csm[(tx * 4 + 0) * 68 + ty * 4 + i] = c0;
        Csm[(tx * 4 + 1) * 68 + ty * 4 + i] = c1;
        Csm[(tx * 4 + 2) * 68 + ty * 4 + i] = c2;
        Csm[(tx * 4 + 3) * 68 + ty * 4 + i] = c3;
    }
    __syncthreads();

    const int nl = tid >> 2;
    const int mq = tid & 3;
    float* dst = g_XP + ((size_t)((t * 5 + mat) * HDIM + hc0 + nl)) * BATCH
                 + brow0 + mq * 16;
    #pragma unroll
    for (int q = 0; q < 4; ++q) {
        float4 v = *(const float4*)&Csm[nl * 68 + mq * 16 + q * 4];
        *(float4*)(dst + q * 4) = v;
    }
}

// ---------------------------------------------------------------------------
// Tagged-stream GEMM: NM matrices x 8 cols x 32 rows over warp w's 32-k slice.
// h elements are {val, tag} pairs; the warp polls its own chunk's tags (data =
// readiness), double-buffered in chunks of 8 k.
// ---------------------------------------------------------------------------
template <int NM>
__device__ __forceinline__ void gemm_warp(
    const ull*  __restrict__ hb,      // tagged h buffer (read side of ring)
    const float* __restrict__ wbase,  // Wsm + first-matrix offset
    float* __restrict__ Gp,           // partials: [w][mat][col*32+row]
    int w, int lane, unsigned tag)
{
    ull acc[NM * 4];
    #pragma unroll
    for (int i = 0; i < NM * 4; ++i) acc[i] = 0ull;

    const ull* hp = hb + (w << 10) + lane;     // element (k = w*32 + i, row=lane)
    const float* wk = wbase + (w * 32) * 8;    // weights for this k-slice

    ull d0[8], d1[8];

    // chunk 0: poll until every lane's 8 tags match
    for (;;) {
        #pragma unroll
        for (int i = 0; i < 8; ++i) d0[i] = ld_rlx64(hp + i * 32);
        bool ok = true;
        #pragma unroll
        for (int i = 0; i < 8; ++i) ok &= ((unsigned)(d0[i] >> 32) == tag);
        if (__ballot_sync(0xffffffffu, ok) == 0xffffffffu) break;
    }

    #pragma unroll
    for (int c = 0; c < 4; ++c) {
        // prefetch next chunk while computing this one
        if (c < 3) {
            #pragma unroll
            for (int i = 0; i < 8; ++i)
                d1[i] = ld_rlx64(hp + ((c + 1) * 8 + i) * 32);
        }
        #pragma unroll
        for (int i = 0; i < 8; ++i) {
            float h = __uint_as_float((unsigned)d0[i]);
            ull hd; PACK2(hd, h);
            #pragma unroll
            for (int m = 0; m < NM; ++m) {
                const float* q = wk + m * 2048 + (c * 8 + i) * 8;
                ulonglong2 wa = *(const ulonglong2*)q;
                ulonglong2 wb = *(const ulonglong2*)(q + 4);
                FMA2(acc[m*4+0], hd, wa.x); FMA2(acc[m*4+1], hd, wa.y);
                FMA2(acc[m*4+2], hd, wb.x); FMA2(acc[m*4+3], hd, wb.y);
            }
        }
        if (c < 3) {
            // verify prefetched chunk; reload until tags match
            for (;;) {
                bool ok = true;
                #pragma unroll
                for (int i = 0; i < 8; ++i)
                    ok &= ((unsigned)(d1[i] >> 32) == tag);
                if (__ballot_sync(0xffffffffu, ok) == 0xffffffffu) break;
                #pragma unroll
                for (int i = 0; i < 8; ++i)
                    d1[i] = ld_rlx64(hp + ((c + 1) * 8 + i) * 32);
            }
            #pragma unroll
            for (int i = 0; i < 8; ++i) d0[i] = d1[i];
        }
    }

    float* gp = Gp + (w * 4) * 256 + lane;
    #pragma unroll
    for (int m = 0; m < NM; ++m) {
        #pragma unroll
        for (int cp = 0; cp < 4; ++cp) {
            float lo, hi;
            UNPK(acc[m*4+cp], lo, hi);
            gp[m*256 + (2*cp)   * 32] = lo;
            gp[m*256 + (2*cp+1) * 32] = hi;
        }
    }
}

// ---------------------------------------------------------------------------
// Kernel 2: the recurrence. 128 CTAs x 256 threads, persistent.
// Dynamic smem: Wsm 16x256x8 (128KB) | Gp 8(w) x 4(mat) x 256 (32KB)
// ---------------------------------------------------------------------------
#define SMEM_FLOATS (NMAT*HDIM*CPC + 8*4*256)
#define SMEM_BYTES  (SMEM_FLOATS * 4)

__global__ void __launch_bounds__(256, 1) rnn_kernel(
    const float* __restrict__ Wr, const float* __restrict__ Wz,
    const float* __restrict__ Wl, const float* __restrict__ Ch,
    const float* __restrict__ Tr, const float* __restrict__ Tz,
    const float* __restrict__ Tn,
    const int*   __restrict__ lengths,
    float*       __restrict__ out)
{
    extern __shared__ float smem[];
    float* Wsm = smem;                       // 32768 floats
    float* Gp  = smem + NMAT * HDIM * CPC;   //  8192 floats

    const int tid  = threadIdx.x;
    const int cta  = blockIdx.x;
    const int g    = cta >> 5;
    const int cb   = cta & 31;
    const int col0 = cb * CPC;

    // ---- load this CTA's 8-column slice of all 16 h-side matrices ----------
    for (int idx = tid; idx < NMAT * HDIM * CPC; idx += 256) {
        int m = idx >> 11;
        int k = (idx >> 3) & 255;
        int c = idx & 7;
        const float* src;
        if (m == 0)      src = Wr + (size_t)(DDIM + k) * HDIM;
        else if (m == 1) src = Wz + (size_t)(DDIM + k) * HDIM;
        else if (m == 2) src = Wl + (size_t)(DDIM + k) * HDIM;
        else if (m == 3) src = Ch + (size_t)k * HDIM;
        else {
            int mm = m - 4, layer = mm / 3, which = mm % 3;
            const float* base = (which == 0) ? Tr : (which == 1) ? Tz : Tn;
            src = base + (size_t)layer * HDIM * HDIM + (size_t)k * HDIM;
        }
        Wsm[idx] = src[col0 + c];
    }
    __syncthreads();

    const int r     = tid & 31;       // batch row within group (also GEMM lane)
    const int cl    = tid >> 5;       // local column (also GEMM warp id)
    const int b     = g * RPG + r;
    const int colg  = col0 + cl;
    const int mylen = lengths[b];
    const int Lg    = lengths[g * RPG];   // sorted descending -> group max

    const int w    = cl;              // warp id
    const int lane = r;

    unsigned p = 0;                   // global phase counter (tag base)
    ull* buf0 = &g_Hbuf[0][g][0];     // tags memset to 0 each launch
    ull* buf1 = &g_Hbuf[1][g][0];

    const int hidx = colg * 32 + r;   // this thread's h element index
    float hown = 0.f;

    for (int t = 0; t < Lg; ++t) {
        const bool act = (t < mylen);
        const float hstep = hown;

        // prefetch this step's x-projections (hidden under phase-A GEMM)
        const float* xp = g_XP + ((size_t)(t * 5) * HDIM + colg) * BATCH + b;
        float xr = __ldcg(xp + 0 * XP_MS);
        float xz = __ldcg(xp + 1 * XP_MS);
        float xl = __ldcg(xp + 2 * XP_MS);
        float xc = __ldcg(xp + 3 * XP_MS);
        float xw = __ldcg(xp + 4 * XP_MS);

        // ================= phase A: 4 GEMMs, warp = k-slice ==================
        {
            const ull* rbuf = (p & 1) ? buf1 : buf0;
            gemm_warp<4>(rbuf, Wsm, Gp, w, lane, p);
        }
        __syncthreads();
        {
            float gr = 0.f, gz = 0.f, gl = 0.f, gch = 0.f;
            #pragma unroll
            for (int ww = 0; ww < 8; ++ww) {
                const float* q = Gp + ww * 1024 + tid;
                gr += q[0]; gz += q[256]; gl += q[512]; gch += q[768];
            }
            float rv = sigmoidf_(xr + gr);
            float zv = sigmoidf_(xz + gz);
            float lv = sigmoidf_(xl + gl);
            float nv = tanhf_(xc + rv * gch) + lv * xw;
            hown = (1.f - zv) * hown + zv * nv;
            ull pk;
            asm("mov.b64 %0,{%1,%2};" : "=l"(pk)
                : "r"(__float_as_uint(hown)), "r"(p + 1));
            st_rlx64(((p & 1) ? buf0 : buf1) + hidx, pk);   // publish
        }
        ++p;
        __syncthreads();   // Gp safe for reuse by next phase's GEMM

        // ================= 4 transition layers (Tr,Tz,Tn) ===================
        #pragma unroll 1
        for (int layer = 0; layer < NLAYERS; ++layer) {
            {
                const ull* rbuf = (p & 1) ? buf1 : buf0;
                gemm_warp<3>(rbuf, Wsm + (4 + 3 * layer) * 2048, Gp, w, lane, p);
            }
            __syncthreads();
            float outval = 0.f;
            bool  dostore = false;
            {
                float grr = 0.f, gzz = 0.f, gnn = 0.f;
                #pragma unroll
                for (int ww = 0; ww < 8; ++ww) {
                    const float* q = Gp + ww * 1024 + tid;
                    grr += q[0]; gzz += q[256]; gnn += q[512];
                }
                float rr = sigmoidf_(grr);
                float zz = sigmoidf_(gzz);
                float nn = tanhf_(rr * gnn);
                float hnew = (1.f - zz) * nn + zz * hown;
                if (layer == NLAYERS - 1) {
                    hown = act ? hnew : hstep;
                    outval  = hnew;
                    dostore = act;
                } else {
                    hown = hnew;
                }
                ull pk;
                asm("mov.b64 %0,{%1,%2};" : "=l"(pk)
                    : "r"(__float_as_uint(hown)), "r"(p + 1));
                st_rlx64(((p & 1) ? buf0 : buf1) + hidx, pk);   // publish
            }
            ++p;
            __syncthreads();
            // output store AFTER publish: off the critical path
            if (dostore)
                out[((size_t)t * BATCH + b) * HDIM + colg] = outval;
        }
    }
}

// ---------------------------------------------------------------------------
// kernel_launch: memsets -> x-projection GEMM -> persistent recurrence
// ---------------------------------------------------------------------------
extern "C" void kernel_launch(void* const* d_in, const int* in_sizes, int n_in,
                              void* d_out, int out_size)
{
    const float* x       = (const float*)d_in[0];
    const int*   lengths = (const int*)  d_in[1];
    const float* Wr      = (const float*)d_in[2];
    const float* Wz      = (const float*)d_in[3];
    const float* Wl      = (const float*)d_in[4];
    const float* Wt      = (const float*)d_in[5];
    const float* Cx      = (const float*)d_in[6];
    const float* Ch      = (const float*)d_in[7];
    const float* Tr      = (const float*)d_in[8];
    const float* Tz      = (const float*)d_in[9];
    const float* Tn      = (const float*)d_in[10];
    float* out = (float*)d_out;
    (void)in_sizes; (void)n_in;

    cudaMemsetAsync(out, 0, (size_t)out_size * sizeof(float));

    // Ring buffer must start with {0.0f, tag=0} every launch: tag 0 == the
    // initial h the first GEMM (phase 0) waits for. Graph-replay safe.
    void* hb_ptr = nullptr;
    cudaGetSymbolAddress(&hb_ptr, g_Hbuf);
    cudaMemsetAsync(hb_ptr, 0, sizeof(ull) * 2 * GROUPS * HDIM * RPG);

    dim3 ggrid(20, 1024);
    xproj_kernel<<<ggrid, 256>>>(x, Wr, Wz, Wl, Cx, Wt);

    cudaFuncSetAttribute(rnn_kernel,
                         cudaFuncAttributeMaxDynamicSharedMemorySize,
                         SMEM_BYTES);
    rnn_kernel<<<GROUPS * CPG, 256, SMEM_BYTES>>>(
        Wr, Wz, Wl, Ch, Tr, Tz, Tn, lengths, out);
}